// round 2
// baseline (speedup 1.0000x reference)
#include <cuda_runtime.h>
#include <cstdint>

#define NN 100000
#define RR 3
#define EE 800000
#define F  128

// ---------------- scratch (device globals: allocation-free rule) ----------
__device__ float g_tmp[(size_t)NN * F];   // per-relation GEMM output
__device__ float g_acc[(size_t)NN * F];   // per-layer aggregation accumulator
__device__ float g_act[(size_t)NN * F];   // layer-1 activations
__device__ float g_ns[RR * NN];           // rsqrt(max(deg_out,1)) per relation
__device__ float g_nd[RR * NN];           // rsqrt(max(deg_in ,1)) per relation

// ---------------- small utility kernels ----------------------------------
__global__ void zero_norms_k() {
    int i = blockIdx.x * blockDim.x + threadIdx.x;
    if (i < RR * NN) { g_ns[i] = 0.f; g_nd[i] = 0.f; }
}

__global__ void zero_acc_k() {
    int i = blockIdx.x * blockDim.x + threadIdx.x;
    int n4 = NN * F / 4;
    if (i < n4) reinterpret_cast<float4*>(g_acc)[i] = make_float4(0.f, 0.f, 0.f, 0.f);
}

__global__ void degree_k(const int* __restrict__ src, const int* __restrict__ dst) {
    int i = blockIdx.x * blockDim.x + threadIdx.x;
    if (i < RR * EE) {
        int r = i / EE;
        atomicAdd(&g_ns[r * NN + src[i]], 1.0f);
        atomicAdd(&g_nd[r * NN + dst[i]], 1.0f);
    }
}

__global__ void norm_fin_k() {
    int i = blockIdx.x * blockDim.x + threadIdx.x;
    if (i < RR * NN) {
        g_ns[i] = rsqrtf(fmaxf(g_ns[i], 1.0f));
        g_nd[i] = rsqrtf(fmaxf(g_nd[i], 1.0f));
    }
}

// ---------------- GEMM: g_tmp = (X @ W) * norm_s[row]  --------------------
// 64 rows x 128 cols per block, 256 threads, 4x8 register tile.
// As is K-major [128][PADA] (transposed on fill), Bs is W verbatim [128][128].
#define BM   64
#define PADA 68
#define GEMM_SMEM ((128 * PADA + 128 * F) * 4)

__global__ void gemm_scale_k(const float* __restrict__ X,
                             const float* __restrict__ W,
                             int r) {
    extern __shared__ float sh[];
    float* As = sh;                 // [k][row], pad 68
    float* Bs = sh + 128 * PADA;    // [k][col]
    const float* ns = g_ns + r * NN;

    int t = threadIdx.x;
    int row0 = blockIdx.x * BM;

    // fill As (transpose X tile): 64x128 floats = 2048 float4, 8 per thread
#pragma unroll
    for (int i = 0; i < 8; i++) {
        int f   = t + 256 * i;
        int row = f >> 5;             // 0..63
        int k4  = (f & 31) << 2;      // 0..124
        int grow = row0 + row;
        float4 v = make_float4(0.f, 0.f, 0.f, 0.f);
        if (grow < NN) v = *reinterpret_cast<const float4*>(X + (size_t)grow * F + k4);
        As[(k4 + 0) * PADA + row] = v.x;
        As[(k4 + 1) * PADA + row] = v.y;
        As[(k4 + 2) * PADA + row] = v.z;
        As[(k4 + 3) * PADA + row] = v.w;
    }
    // fill Bs: 128x128 = 4096 float4, 16 per thread (W is already [k][col])
#pragma unroll
    for (int i = 0; i < 16; i++) {
        int f  = t + 256 * i;
        int k  = f >> 5;
        int c4 = (f & 31) << 2;
        *reinterpret_cast<float4*>(Bs + k * F + c4) =
            *reinterpret_cast<const float4*>(W + k * F + c4);
    }
    __syncthreads();

    int tx = t & 15;      // col group: cols tx*8 .. tx*8+7
    int ty = t >> 4;      // row group: rows ty*4 .. ty*4+3

    float acc[4][8];
#pragma unroll
    for (int i = 0; i < 4; i++)
#pragma unroll
        for (int j = 0; j < 8; j++) acc[i][j] = 0.f;

#pragma unroll 8
    for (int k = 0; k < 128; k++) {
        float4 a  = *reinterpret_cast<const float4*>(As + k * PADA + ty * 4);
        float4 b0 = *reinterpret_cast<const float4*>(Bs + k * F + tx * 8);
        float4 b1 = *reinterpret_cast<const float4*>(Bs + k * F + tx * 8 + 4);
        float av[4] = {a.x, a.y, a.z, a.w};
        float bv[8] = {b0.x, b0.y, b0.z, b0.w, b1.x, b1.y, b1.z, b1.w};
#pragma unroll
        for (int i = 0; i < 4; i++)
#pragma unroll
            for (int j = 0; j < 8; j++) acc[i][j] += av[i] * bv[j];
    }

#pragma unroll
    for (int i = 0; i < 4; i++) {
        int grow = row0 + ty * 4 + i;
        if (grow < NN) {
            float s = ns[grow];
            float4 o0 = make_float4(acc[i][0] * s, acc[i][1] * s, acc[i][2] * s, acc[i][3] * s);
            float4 o1 = make_float4(acc[i][4] * s, acc[i][5] * s, acc[i][6] * s, acc[i][7] * s);
            *reinterpret_cast<float4*>(g_tmp + (size_t)grow * F + tx * 8)     = o0;
            *reinterpret_cast<float4*>(g_tmp + (size_t)grow * F + tx * 8 + 4) = o1;
        }
    }
}

// ---------------- edge scatter: g_acc[dst] += g_tmp[src] * norm_d[dst] ----
// one warp per edge, 32 lanes x float4 = 128 floats, vector RED (no return)
__global__ void scatter_k(const int* __restrict__ src,
                          const int* __restrict__ dst,
                          int r) {
    int gid  = blockIdx.x * blockDim.x + threadIdx.x;
    int e    = gid >> 5;
    int lane = gid & 31;
    if (e >= EE) return;
    int s = src[e];
    int d = dst[e];
    float sc = __ldg(&g_nd[r * NN + d]);
    float4 v = *reinterpret_cast<const float4*>(g_tmp + (size_t)s * F + lane * 4);
    float* p = g_acc + (size_t)d * F + lane * 4;
    asm volatile("red.global.add.v4.f32 [%0], {%1, %2, %3, %4};"
                 :: "l"(p), "f"(v.x * sc), "f"(v.y * sc), "f"(v.z * sc), "f"(v.w * sc)
                 : "memory");
}

// ---------------- finalize: out = acc + sum_r b[r]  (+ optional ReLU) -----
__global__ void finalize_k(const float* __restrict__ b,
                           float* __restrict__ out,
                           int relu) {
    int i = blockIdx.x * blockDim.x + threadIdx.x;
    if (i < NN * F) {
        int j = i & 127;
        float v = g_acc[i] + b[j] + b[F + j] + b[2 * F + j];
        if (relu) v = fmaxf(v, 0.f);
        out[i] = v;
    }
}

// ---------------- launch ---------------------------------------------------
extern "C" void kernel_launch(void* const* d_in, const int* in_sizes, int n_in,
                              void* d_out, int out_size) {
    const float* x   = (const float*)d_in[0];
    const int*   src = (const int*)  d_in[1];
    const int*   dst = (const int*)  d_in[2];
    const float* W1  = (const float*)d_in[3];
    const float* b1  = (const float*)d_in[4];
    const float* W2  = (const float*)d_in[5];
    const float* b2  = (const float*)d_in[6];
    float* out = (float*)d_out;

    void* p_act = nullptr;
    cudaGetSymbolAddress(&p_act, g_act);
    float* act = (float*)p_act;

    cudaFuncSetAttribute(gemm_scale_k,
                         cudaFuncAttributeMaxDynamicSharedMemorySize, GEMM_SMEM);

    const int T = 256;
    // degrees -> norms (shared by both layers)
    zero_norms_k<<<(RR * NN + T - 1) / T, T>>>();
    degree_k<<<(RR * EE + T - 1) / T, T>>>(src, dst);
    norm_fin_k<<<(RR * NN + T - 1) / T, T>>>();

    int gemm_blocks    = (NN + BM - 1) / BM;
    int scatter_blocks = (EE * 32 + T - 1) / T;
    int elem_blocks    = (NN * F + T - 1) / T;

    // ---- layer 1 ----
    zero_acc_k<<<(NN * F / 4 + T - 1) / T, T>>>();
    for (int r = 0; r < RR; r++) {
        gemm_scale_k<<<gemm_blocks, T, GEMM_SMEM>>>(x, W1 + (size_t)r * F * F, r);
        scatter_k<<<scatter_blocks, T>>>(src + (size_t)r * EE, dst + (size_t)r * EE, r);
    }
    finalize_k<<<elem_blocks, T>>>(b1, act, 1);

    // ---- layer 2 ----
    zero_acc_k<<<(NN * F / 4 + T - 1) / T, T>>>();
    for (int r = 0; r < RR; r++) {
        gemm_scale_k<<<gemm_blocks, T, GEMM_SMEM>>>(act, W2 + (size_t)r * F * F, r);
        scatter_k<<<scatter_blocks, T>>>(src + (size_t)r * EE, dst + (size_t)r * EE, r);
    }
    finalize_k<<<elem_blocks, T>>>(b2, out, 0);
}

// round 3
// speedup vs baseline: 1.5073x; 1.5073x over previous
#include <cuda_runtime.h>
#include <cuda_bf16.h>
#include <cstdint>

#define NN 100000
#define RR 3
#define EE 800000
#define F  128

// ---------------- scratch (device globals: allocation-free rule) ----------
__device__ float g_tmp[(size_t)NN * F];   // per-relation GEMM output
__device__ float g_acc[(size_t)NN * F];   // per-layer aggregation accumulator
__device__ float g_act[(size_t)NN * F];   // layer-1 activations
__device__ float g_ns[RR * NN];           // rsqrt(max(deg_out,1)) per relation
__device__ float g_nd[RR * NN];           // rsqrt(max(deg_in ,1)) per relation

// ---------------- small utility kernels ----------------------------------
__global__ void zero_norms_k() {
    int i = blockIdx.x * blockDim.x + threadIdx.x;
    if (i < RR * NN) { g_ns[i] = 0.f; g_nd[i] = 0.f; }
}

__global__ void zero_acc_k() {
    int i = blockIdx.x * blockDim.x + threadIdx.x;
    int n4 = NN * F / 4;
    if (i < n4) reinterpret_cast<float4*>(g_acc)[i] = make_float4(0.f, 0.f, 0.f, 0.f);
}

__global__ void degree_k(const int* __restrict__ src, const int* __restrict__ dst) {
    int i = blockIdx.x * blockDim.x + threadIdx.x;
    if (i < RR * EE) {
        int r = i / EE;
        atomicAdd(&g_ns[r * NN + src[i]], 1.0f);
        atomicAdd(&g_nd[r * NN + dst[i]], 1.0f);
    }
}

__global__ void norm_fin_k() {
    int i = blockIdx.x * blockDim.x + threadIdx.x;
    if (i < RR * NN) {
        g_ns[i] = rsqrtf(fmaxf(g_ns[i], 1.0f));
        g_nd[i] = rsqrtf(fmaxf(g_nd[i], 1.0f));
    }
}

// ---------------- tensor-core GEMM (bf16 3-term split) --------------------
// g_tmp = (X @ W) * norm_s[row].  128x128 tile per block, 256 threads (8 warps,
// 4x2), warp tile 32x64.  mma.sync.m16n8k16 bf16, fp32 accum.
// A smem: [m=128][k=136 pad] bf16 (hi & lo planes), ldmatrix (non-trans).
// B smem: [k=128][n=136 pad] bf16 (hi & lo planes), ldmatrix.trans.
#define PA   136
#define PLANE (128 * PA)
#define GEMM_SMEM (4 * PLANE * 2)

#define MMA_BF16(d, a, b) \
    asm volatile("mma.sync.aligned.m16n8k16.row.col.f32.bf16.bf16.f32 " \
                 "{%0,%1,%2,%3}, {%4,%5,%6,%7}, {%8,%9}, {%0,%1,%2,%3};" \
                 : "+f"((d)[0]), "+f"((d)[1]), "+f"((d)[2]), "+f"((d)[3]) \
                 : "r"((a)[0]), "r"((a)[1]), "r"((a)[2]), "r"((a)[3]), \
                   "r"((b)[0]), "r"((b)[1]))

#define LDSM_X4(r, addr) \
    asm volatile("ldmatrix.sync.aligned.m8n8.x4.shared.b16 {%0,%1,%2,%3}, [%4];" \
                 : "=r"((r)[0]), "=r"((r)[1]), "=r"((r)[2]), "=r"((r)[3]) \
                 : "r"(addr))

#define LDSM_X4_T(r, addr) \
    asm volatile("ldmatrix.sync.aligned.m8n8.x4.trans.shared.b16 {%0,%1,%2,%3}, [%4];" \
                 : "=r"((r)[0]), "=r"((r)[1]), "=r"((r)[2]), "=r"((r)[3]) \
                 : "r"(addr))

__device__ __forceinline__ void split2(float x, float y,
                                       __nv_bfloat162& hi, __nv_bfloat162& lo) {
    __nv_bfloat16 hx = __float2bfloat16_rn(x);
    __nv_bfloat16 hy = __float2bfloat16_rn(y);
    hi.x = hx; hi.y = hy;
    lo.x = __float2bfloat16_rn(x - __bfloat162float(hx));
    lo.y = __float2bfloat16_rn(y - __bfloat162float(hy));
}

__global__ void __launch_bounds__(256)
gemm_tc_k(const float* __restrict__ X, const float* __restrict__ W, int r) {
    extern __shared__ __align__(16) __nv_bfloat16 sh[];
    __nv_bfloat16* Ah = sh;               // [m][k] pad PA
    __nv_bfloat16* Al = sh + PLANE;
    __nv_bfloat16* Bh = sh + 2 * PLANE;   // [k][n] pad PA
    __nv_bfloat16* Bl = sh + 3 * PLANE;

    int t = threadIdx.x;
    int row0 = blockIdx.x * 128;

    // ---- fill A: 128x128 fp32 -> bf16 hi/lo, [m][k] ----
#pragma unroll
    for (int i = 0; i < 16; i++) {
        int f   = t + 256 * i;
        int row = f >> 5;
        int c4  = (f & 31) << 2;
        int grow = row0 + row;
        float4 v = make_float4(0.f, 0.f, 0.f, 0.f);
        if (grow < NN) v = *reinterpret_cast<const float4*>(X + (size_t)grow * F + c4);
        __nv_bfloat162 h0, l0, h1, l1;
        split2(v.x, v.y, h0, l0);
        split2(v.z, v.w, h1, l1);
        int base = row * PA + c4;
        *reinterpret_cast<__nv_bfloat162*>(&Ah[base])     = h0;
        *reinterpret_cast<__nv_bfloat162*>(&Ah[base + 2]) = h1;
        *reinterpret_cast<__nv_bfloat162*>(&Al[base])     = l0;
        *reinterpret_cast<__nv_bfloat162*>(&Al[base + 2]) = l1;
    }
    // ---- fill B: W is [k][n] row-major, copy straight ----
#pragma unroll
    for (int i = 0; i < 16; i++) {
        int f  = t + 256 * i;
        int k  = f >> 5;
        int n4 = (f & 31) << 2;
        float4 v = *reinterpret_cast<const float4*>(W + (size_t)k * F + n4);
        __nv_bfloat162 h0, l0, h1, l1;
        split2(v.x, v.y, h0, l0);
        split2(v.z, v.w, h1, l1);
        int base = k * PA + n4;
        *reinterpret_cast<__nv_bfloat162*>(&Bh[base])     = h0;
        *reinterpret_cast<__nv_bfloat162*>(&Bh[base + 2]) = h1;
        *reinterpret_cast<__nv_bfloat162*>(&Bl[base])     = l0;
        *reinterpret_cast<__nv_bfloat162*>(&Bl[base + 2]) = l1;
    }
    __syncthreads();

    int lane = t & 31, warp = t >> 5;
    int mbase = (warp & 3) * 32;   // warp covers rows mbase..mbase+31
    int nbase = (warp >> 2) * 64;  // cols nbase..nbase+63

    // ldmatrix lane -> (row, offset) mapping
    int lrow = lane & 7;
    int m8   = ((lane >> 3) & 1) << 3;   // mats 1,3: +8 rows
    int k8   = ((lane >> 4) & 1) << 3;   // mats 2,3: +8 k

    // A addresses (per mt), bytes; advance +32B per k-chunk
    unsigned aA0 = (unsigned)__cvta_generic_to_shared(
        &Ah[(mbase + lrow + m8) * PA + k8]);
    unsigned aA1 = aA0 + 16 * PA * 2;            // mt=1: +16 rows
    unsigned aLoOff = PLANE * 2;                 // Ah -> Al byte offset

    // B addresses (per n-pair): mats {k,+8k} x {n,+8n}; advance +16*PA*2 per kc
    unsigned aB0 = (unsigned)__cvta_generic_to_shared(
        &Bh[(lrow + m8) * PA + nbase + k8]);     // here m8 = +8 k-rows, k8 = +8 n
    // note: for B, "m8" selects k+8 (mats 1,3), "k8" selects n+8 (mats 2,3)

    float acc[2][8][4];
#pragma unroll
    for (int mt = 0; mt < 2; mt++)
#pragma unroll
        for (int nt = 0; nt < 8; nt++)
#pragma unroll
            for (int c = 0; c < 4; c++) acc[mt][nt][c] = 0.f;

#pragma unroll
    for (int kc = 0; kc < 8; kc++) {
        unsigned aOff = kc * 32;                 // 16 bf16 = 32 B along k
        unsigned bOff = kc * 16 * PA * 2;        // 16 k-rows

        unsigned ah[2][4], al[2][4];
        LDSM_X4(ah[0], aA0 + aOff);
        LDSM_X4(ah[1], aA1 + aOff);
        LDSM_X4(al[0], aA0 + aLoOff + aOff);
        LDSM_X4(al[1], aA1 + aLoOff + aOff);

#pragma unroll
        for (int np = 0; np < 4; np++) {
            unsigned bAddr = aB0 + bOff + np * 16 * 2;   // +16 n per pair
            unsigned bh[4], bl[4];
            LDSM_X4_T(bh, bAddr);
            LDSM_X4_T(bl, bAddr + aLoOff);
            unsigned* bh0 = bh;     // n-tile 2*np
            unsigned* bh1 = bh + 2; // n-tile 2*np+1
            unsigned* bl0 = bl;
            unsigned* bl1 = bl + 2;
#pragma unroll
            for (int mt = 0; mt < 2; mt++) {
                MMA_BF16(acc[mt][2 * np],     ah[mt], bh0);
                MMA_BF16(acc[mt][2 * np],     ah[mt], bl0);
                MMA_BF16(acc[mt][2 * np],     al[mt], bh0);
                MMA_BF16(acc[mt][2 * np + 1], ah[mt], bh1);
                MMA_BF16(acc[mt][2 * np + 1], ah[mt], bl1);
                MMA_BF16(acc[mt][2 * np + 1], al[mt], bh1);
            }
        }
    }

    // ---- epilogue: scale by norm_s[row], store fp32 ----
    const float* ns = g_ns + r * NN;
    int grp = lane >> 2;
    int cof = (lane & 3) * 2;
#pragma unroll
    for (int mt = 0; mt < 2; mt++) {
        int rA = row0 + mbase + mt * 16 + grp;
        int rB = rA + 8;
        float sA = (rA < NN) ? ns[rA] : 0.f;
        float sB = (rB < NN) ? ns[rB] : 0.f;
#pragma unroll
        for (int nt = 0; nt < 8; nt++) {
            int col = nbase + nt * 8 + cof;
            if (rA < NN) {
                float2 o = make_float2(acc[mt][nt][0] * sA, acc[mt][nt][1] * sA);
                *reinterpret_cast<float2*>(g_tmp + (size_t)rA * F + col) = o;
            }
            if (rB < NN) {
                float2 o = make_float2(acc[mt][nt][2] * sB, acc[mt][nt][3] * sB);
                *reinterpret_cast<float2*>(g_tmp + (size_t)rB * F + col) = o;
            }
        }
    }
}

// ---------------- edge scatter: g_acc[dst] += g_tmp[src] * norm_d[dst] ----
__global__ void scatter_k(const int* __restrict__ src,
                          const int* __restrict__ dst,
                          int r) {
    int gid  = blockIdx.x * blockDim.x + threadIdx.x;
    int e    = gid >> 5;
    int lane = gid & 31;
    if (e >= EE) return;
    int s = src[e];
    int d = dst[e];
    float sc = __ldg(&g_nd[r * NN + d]);
    float4 v = *reinterpret_cast<const float4*>(g_tmp + (size_t)s * F + lane * 4);
    float* p = g_acc + (size_t)d * F + lane * 4;
    asm volatile("red.global.add.v4.f32 [%0], {%1, %2, %3, %4};"
                 :: "l"(p), "f"(v.x * sc), "f"(v.y * sc), "f"(v.z * sc), "f"(v.w * sc)
                 : "memory");
}

// ---------------- finalize: out = acc + sum_r b[r]  (+ optional ReLU) -----
__global__ void finalize_k(const float* __restrict__ b,
                           float* __restrict__ out,
                           int relu) {
    int i = blockIdx.x * blockDim.x + threadIdx.x;
    if (i < NN * F) {
        int j = i & 127;
        float v = g_acc[i] + b[j] + b[F + j] + b[2 * F + j];
        if (relu) v = fmaxf(v, 0.f);
        out[i] = v;
    }
}

// ---------------- launch ---------------------------------------------------
extern "C" void kernel_launch(void* const* d_in, const int* in_sizes, int n_in,
                              void* d_out, int out_size) {
    const float* x   = (const float*)d_in[0];
    const int*   src = (const int*)  d_in[1];
    const int*   dst = (const int*)  d_in[2];
    const float* W1  = (const float*)d_in[3];
    const float* b1  = (const float*)d_in[4];
    const float* W2  = (const float*)d_in[5];
    const float* b2  = (const float*)d_in[6];
    float* out = (float*)d_out;

    void* p_act = nullptr;
    cudaGetSymbolAddress(&p_act, g_act);
    float* act = (float*)p_act;

    cudaFuncSetAttribute(gemm_tc_k,
                         cudaFuncAttributeMaxDynamicSharedMemorySize, GEMM_SMEM);

    const int T = 256;
    zero_norms_k<<<(RR * NN + T - 1) / T, T>>>();
    degree_k<<<(RR * EE + T - 1) / T, T>>>(src, dst);
    norm_fin_k<<<(RR * NN + T - 1) / T, T>>>();

    int gemm_blocks    = (NN + 127) / 128;
    int scatter_blocks = (EE * 32 + T - 1) / T;
    int elem_blocks    = (NN * F + T - 1) / T;

    // ---- layer 1 ----
    zero_acc_k<<<(NN * F / 4 + T - 1) / T, T>>>();
    for (int r = 0; r < RR; r++) {
        gemm_tc_k<<<gemm_blocks, T, GEMM_SMEM>>>(x, W1 + (size_t)r * F * F, r);
        scatter_k<<<scatter_blocks, T>>>(src + (size_t)r * EE, dst + (size_t)r * EE, r);
    }
    finalize_k<<<elem_blocks, T>>>(b1, act, 1);

    // ---- layer 2 ----
    zero_acc_k<<<(NN * F / 4 + T - 1) / T, T>>>();
    for (int r = 0; r < RR; r++) {
        gemm_tc_k<<<gemm_blocks, T, GEMM_SMEM>>>(act, W2 + (size_t)r * F * F, r);
        scatter_k<<<scatter_blocks, T>>>(src + (size_t)r * EE, dst + (size_t)r * EE, r);
    }
    finalize_k<<<elem_blocks, T>>>(b2, out, 0);
}

// round 4
// speedup vs baseline: 1.9445x; 1.2900x over previous
#include <cuda_runtime.h>
#include <cuda_bf16.h>
#include <cstdint>

#define NN 100000
#define RR 3
#define EE 800000
#define F  128

// ---------------- scratch (device globals: allocation-free rule) ----------
__device__ float g_tmp3[(size_t)RR * NN * F]; // per-relation GEMM outputs
__device__ float g_acc[(size_t)NN * F];       // layer partial accumulator
__device__ float g_act[(size_t)NN * F];       // layer-1 activations
__device__ float g_ns[RR * NN];               // rsqrt(max(deg_out,1))
__device__ float g_nd[RR * NN];               // counts, then rsqrt(max(deg_in,1))
__device__ int   g_off[RR * NN];              // CSR offsets (per relation, by dst)
__device__ int   g_degi[RR * NN];             // int in-degree
__device__ int   g_cur[RR * NN];              // bucket cursors
__device__ int   g_csrc[(size_t)RR * EE];     // dst-sorted src indices

// ---------------- small utility kernels ----------------------------------
__global__ void zero_norms_k() {
    int i = blockIdx.x * blockDim.x + threadIdx.x;
    if (i < RR * NN) { g_ns[i] = 0.f; g_nd[i] = 0.f; g_cur[i] = 0; }
}

__global__ void degree_k(const int* __restrict__ src, const int* __restrict__ dst) {
    int i = blockIdx.x * blockDim.x + threadIdx.x;
    if (i < RR * EE) {
        int r = i / EE;
        atomicAdd(&g_ns[r * NN + src[i]], 1.0f);
        atomicAdd(&g_nd[r * NN + dst[i]], 1.0f);
    }
}

// exclusive scan of int(g_nd[r]) over NN -> g_off[r], also g_degi. 1 block/rel.
__global__ void scan_k() {
    __shared__ int sh[1024];
    int r = blockIdx.x, t = threadIdx.x;
    const float* deg = g_nd + r * NN;
    const int CH = (NN + 1023) / 1024;   // 98
    int base = t * CH;
    int s = 0;
    for (int i = 0; i < CH; i++) {
        int idx = base + i;
        if (idx < NN) s += (int)deg[idx];
    }
    sh[t] = s;
    __syncthreads();
    // inclusive Hillis-Steele
    for (int off = 1; off < 1024; off <<= 1) {
        int v = (t >= off) ? sh[t - off] : 0;
        __syncthreads();
        sh[t] += v;
        __syncthreads();
    }
    int run = sh[t] - s;   // exclusive prefix of this chunk
    for (int i = 0; i < CH; i++) {
        int idx = base + i;
        if (idx < NN) {
            int d = (int)deg[idx];
            g_off[r * NN + idx]  = run;
            g_degi[r * NN + idx] = d;
            run += d;
        }
    }
}

__global__ void norm_fin_k() {
    int i = blockIdx.x * blockDim.x + threadIdx.x;
    if (i < RR * NN) {
        g_ns[i] = rsqrtf(fmaxf(g_ns[i], 1.0f));
        g_nd[i] = rsqrtf(fmaxf(g_nd[i], 1.0f));
    }
}

__global__ void fill_csr_k(const int* __restrict__ src, const int* __restrict__ dst) {
    int i = blockIdx.x * blockDim.x + threadIdx.x;
    if (i < RR * EE) {
        int r = i / EE;
        int d = dst[i];
        int pos = atomicAdd(&g_cur[r * NN + d], 1);
        g_csrc[(size_t)r * EE + g_off[r * NN + d] + pos] = src[i];
    }
}

// ---------------- tensor-core GEMM (bf16 3-term split) --------------------
#define PA   136
#define PLANE (128 * PA)
#define GEMM_SMEM (4 * PLANE * 2)

#define MMA_BF16(d, a, b) \
    asm volatile("mma.sync.aligned.m16n8k16.row.col.f32.bf16.bf16.f32 " \
                 "{%0,%1,%2,%3}, {%4,%5,%6,%7}, {%8,%9}, {%0,%1,%2,%3};" \
                 : "+f"((d)[0]), "+f"((d)[1]), "+f"((d)[2]), "+f"((d)[3]) \
                 : "r"((a)[0]), "r"((a)[1]), "r"((a)[2]), "r"((a)[3]), \
                   "r"((b)[0]), "r"((b)[1]))

#define LDSM_X4(r, addr) \
    asm volatile("ldmatrix.sync.aligned.m8n8.x4.shared.b16 {%0,%1,%2,%3}, [%4];" \
                 : "=r"((r)[0]), "=r"((r)[1]), "=r"((r)[2]), "=r"((r)[3]) \
                 : "r"(addr))

#define LDSM_X4_T(r, addr) \
    asm volatile("ldmatrix.sync.aligned.m8n8.x4.trans.shared.b16 {%0,%1,%2,%3}, [%4];" \
                 : "=r"((r)[0]), "=r"((r)[1]), "=r"((r)[2]), "=r"((r)[3]) \
                 : "r"(addr))

__device__ __forceinline__ void split2(float x, float y,
                                       __nv_bfloat162& hi, __nv_bfloat162& lo) {
    __nv_bfloat16 hx = __float2bfloat16_rn(x);
    __nv_bfloat16 hy = __float2bfloat16_rn(y);
    hi.x = hx; hi.y = hy;
    lo.x = __float2bfloat16_rn(x - __bfloat162float(hx));
    lo.y = __float2bfloat16_rn(y - __bfloat162float(hy));
}

__global__ void __launch_bounds__(256)
gemm_tc_k(const float* __restrict__ X, const float* __restrict__ W,
          const float* __restrict__ ns, float* __restrict__ outp) {
    extern __shared__ __align__(16) __nv_bfloat16 sh[];
    __nv_bfloat16* Ah = sh;
    __nv_bfloat16* Al = sh + PLANE;
    __nv_bfloat16* Bh = sh + 2 * PLANE;
    __nv_bfloat16* Bl = sh + 3 * PLANE;

    int t = threadIdx.x;
    int row0 = blockIdx.x * 128;

#pragma unroll
    for (int i = 0; i < 16; i++) {
        int f   = t + 256 * i;
        int row = f >> 5;
        int c4  = (f & 31) << 2;
        int grow = row0 + row;
        float4 v = make_float4(0.f, 0.f, 0.f, 0.f);
        if (grow < NN) v = *reinterpret_cast<const float4*>(X + (size_t)grow * F + c4);
        __nv_bfloat162 h0, l0, h1, l1;
        split2(v.x, v.y, h0, l0);
        split2(v.z, v.w, h1, l1);
        int base = row * PA + c4;
        *reinterpret_cast<__nv_bfloat162*>(&Ah[base])     = h0;
        *reinterpret_cast<__nv_bfloat162*>(&Ah[base + 2]) = h1;
        *reinterpret_cast<__nv_bfloat162*>(&Al[base])     = l0;
        *reinterpret_cast<__nv_bfloat162*>(&Al[base + 2]) = l1;
    }
#pragma unroll
    for (int i = 0; i < 16; i++) {
        int f  = t + 256 * i;
        int k  = f >> 5;
        int n4 = (f & 31) << 2;
        float4 v = *reinterpret_cast<const float4*>(W + (size_t)k * F + n4);
        __nv_bfloat162 h0, l0, h1, l1;
        split2(v.x, v.y, h0, l0);
        split2(v.z, v.w, h1, l1);
        int base = k * PA + n4;
        *reinterpret_cast<__nv_bfloat162*>(&Bh[base])     = h0;
        *reinterpret_cast<__nv_bfloat162*>(&Bh[base + 2]) = h1;
        *reinterpret_cast<__nv_bfloat162*>(&Bl[base])     = l0;
        *reinterpret_cast<__nv_bfloat162*>(&Bl[base + 2]) = l1;
    }
    __syncthreads();

    int lane = t & 31, warp = t >> 5;
    int mbase = (warp & 3) * 32;
    int nbase = (warp >> 2) * 64;

    int lrow = lane & 7;
    int m8   = ((lane >> 3) & 1) << 3;
    int k8   = ((lane >> 4) & 1) << 3;

    unsigned aA0 = (unsigned)__cvta_generic_to_shared(
        &Ah[(mbase + lrow + m8) * PA + k8]);
    unsigned aA1 = aA0 + 16 * PA * 2;
    unsigned aLoOff = PLANE * 2;

    unsigned aB0 = (unsigned)__cvta_generic_to_shared(
        &Bh[(lrow + m8) * PA + nbase + k8]);

    float acc[2][8][4];
#pragma unroll
    for (int mt = 0; mt < 2; mt++)
#pragma unroll
        for (int nt = 0; nt < 8; nt++)
#pragma unroll
            for (int c = 0; c < 4; c++) acc[mt][nt][c] = 0.f;

#pragma unroll
    for (int kc = 0; kc < 8; kc++) {
        unsigned aOff = kc * 32;
        unsigned bOff = kc * 16 * PA * 2;

        unsigned ah[2][4], al[2][4];
        LDSM_X4(ah[0], aA0 + aOff);
        LDSM_X4(ah[1], aA1 + aOff);
        LDSM_X4(al[0], aA0 + aLoOff + aOff);
        LDSM_X4(al[1], aA1 + aLoOff + aOff);

#pragma unroll
        for (int np = 0; np < 4; np++) {
            unsigned bAddr = aB0 + bOff + np * 16 * 2;
            unsigned bh[4], bl[4];
            LDSM_X4_T(bh, bAddr);
            LDSM_X4_T(bl, bAddr + aLoOff);
            unsigned* bh0 = bh;
            unsigned* bh1 = bh + 2;
            unsigned* bl0 = bl;
            unsigned* bl1 = bl + 2;
#pragma unroll
            for (int mt = 0; mt < 2; mt++) {
                MMA_BF16(acc[mt][2 * np],     ah[mt], bh0);
                MMA_BF16(acc[mt][2 * np],     ah[mt], bl0);
                MMA_BF16(acc[mt][2 * np],     al[mt], bh0);
                MMA_BF16(acc[mt][2 * np + 1], ah[mt], bh1);
                MMA_BF16(acc[mt][2 * np + 1], ah[mt], bl1);
                MMA_BF16(acc[mt][2 * np + 1], al[mt], bh1);
            }
        }
    }

    int grp = lane >> 2;
    int cof = (lane & 3) * 2;
#pragma unroll
    for (int mt = 0; mt < 2; mt++) {
        int rA = row0 + mbase + mt * 16 + grp;
        int rB = rA + 8;
        float sA = (rA < NN) ? ns[rA] : 0.f;
        float sB = (rB < NN) ? ns[rB] : 0.f;
#pragma unroll
        for (int nt = 0; nt < 8; nt++) {
            int col = nbase + nt * 8 + cof;
            if (rA < NN) {
                float2 o = make_float2(acc[mt][nt][0] * sA, acc[mt][nt][1] * sA);
                *reinterpret_cast<float2*>(outp + (size_t)rA * F + col) = o;
            }
            if (rB < NN) {
                float2 o = make_float2(acc[mt][nt][2] * sB, acc[mt][nt][3] * sB);
                *reinterpret_cast<float2*>(outp + (size_t)rB * F + col) = o;
            }
        }
    }
}

// ---------------- CSR aggregation: one warp per dst node ------------------
// pass r: acc = (sum_{e in CSR[r][node]} tmp_r[src_e]) * nd_r[node]
// first pass writes g_acc, middle pass RMWs, last pass adds bias(+relu) -> out
__global__ void __launch_bounds__(256)
agg_k(int r, const float* __restrict__ tmp, const float* __restrict__ bias,
      float* __restrict__ outp, int first, int last, int relu) {
    int warp = (blockIdx.x * blockDim.x + threadIdx.x) >> 5;
    int lane = threadIdx.x & 31;
    if (warp >= NN) return;
    int node = warp;

    int off = g_off[r * NN + node];
    int cnt = g_degi[r * NN + node];
    const int* lst = g_csrc + (size_t)r * EE + off;

    float4 acc = make_float4(0.f, 0.f, 0.f, 0.f);
    int c4 = lane * 4;

    int j = 0;
    for (; j + 4 <= cnt; j += 4) {
        int s0 = __ldg(lst + j);
        int s1 = __ldg(lst + j + 1);
        int s2 = __ldg(lst + j + 2);
        int s3 = __ldg(lst + j + 3);
        float4 v0 = *reinterpret_cast<const float4*>(tmp + (size_t)s0 * F + c4);
        float4 v1 = *reinterpret_cast<const float4*>(tmp + (size_t)s1 * F + c4);
        float4 v2 = *reinterpret_cast<const float4*>(tmp + (size_t)s2 * F + c4);
        float4 v3 = *reinterpret_cast<const float4*>(tmp + (size_t)s3 * F + c4);
        acc.x += v0.x + v1.x + v2.x + v3.x;
        acc.y += v0.y + v1.y + v2.y + v3.y;
        acc.z += v0.z + v1.z + v2.z + v3.z;
        acc.w += v0.w + v1.w + v2.w + v3.w;
    }
    for (; j < cnt; j++) {
        int s = __ldg(lst + j);
        float4 v = *reinterpret_cast<const float4*>(tmp + (size_t)s * F + c4);
        acc.x += v.x; acc.y += v.y; acc.z += v.z; acc.w += v.w;
    }

    float nd = g_nd[r * NN + node];
    acc.x *= nd; acc.y *= nd; acc.z *= nd; acc.w *= nd;

    float* accp = g_acc + (size_t)node * F + c4;
    if (!first) {
        float4 p = *reinterpret_cast<float4*>(accp);
        acc.x += p.x; acc.y += p.y; acc.z += p.z; acc.w += p.w;
    }
    if (last) {
        float4 b0 = *reinterpret_cast<const float4*>(bias + c4);
        float4 b1 = *reinterpret_cast<const float4*>(bias + F + c4);
        float4 b2 = *reinterpret_cast<const float4*>(bias + 2 * F + c4);
        acc.x += b0.x + b1.x + b2.x;
        acc.y += b0.y + b1.y + b2.y;
        acc.z += b0.z + b1.z + b2.z;
        acc.w += b0.w + b1.w + b2.w;
        if (relu) {
            acc.x = fmaxf(acc.x, 0.f); acc.y = fmaxf(acc.y, 0.f);
            acc.z = fmaxf(acc.z, 0.f); acc.w = fmaxf(acc.w, 0.f);
        }
        *reinterpret_cast<float4*>(outp + (size_t)node * F + c4) = acc;
    } else {
        *reinterpret_cast<float4*>(accp) = acc;
    }
}

// ---------------- launch ---------------------------------------------------
extern "C" void kernel_launch(void* const* d_in, const int* in_sizes, int n_in,
                              void* d_out, int out_size) {
    const float* x   = (const float*)d_in[0];
    const int*   src = (const int*)  d_in[1];
    const int*   dst = (const int*)  d_in[2];
    const float* W1  = (const float*)d_in[3];
    const float* b1  = (const float*)d_in[4];
    const float* W2  = (const float*)d_in[5];
    const float* b2  = (const float*)d_in[6];
    float* out = (float*)d_out;

    void* p;
    cudaGetSymbolAddress(&p, g_act);  float* act = (float*)p;
    cudaGetSymbolAddress(&p, g_tmp3); float* tmp = (float*)p;
    cudaGetSymbolAddress(&p, g_ns);   float* ns  = (float*)p;

    cudaFuncSetAttribute(gemm_tc_k,
                         cudaFuncAttributeMaxDynamicSharedMemorySize, GEMM_SMEM);

    const int T = 256;
    zero_norms_k<<<(RR * NN + T - 1) / T, T>>>();
    degree_k<<<(RR * EE + T - 1) / T, T>>>(src, dst);
    scan_k<<<RR, 1024>>>();
    norm_fin_k<<<(RR * NN + T - 1) / T, T>>>();
    fill_csr_k<<<(RR * EE + T - 1) / T, T>>>(src, dst);

    int gemm_blocks = (NN + 127) / 128;
    int agg_blocks  = (NN + 7) / 8;   // 8 warps/block, 1 warp/node

    // ---- layer 1 ----
    for (int r = 0; r < RR; r++)
        gemm_tc_k<<<gemm_blocks, T, GEMM_SMEM>>>(
            x, W1 + (size_t)r * F * F, ns + (size_t)r * NN, tmp + (size_t)r * NN * F);
    for (int r = 0; r < RR; r++)
        agg_k<<<agg_blocks, T>>>(r, tmp + (size_t)r * NN * F, b1, act,
                                 r == 0, r == RR - 1, 1);

    // ---- layer 2 ----
    for (int r = 0; r < RR; r++)
        gemm_tc_k<<<gemm_blocks, T, GEMM_SMEM>>>(
            act, W2 + (size_t)r * F * F, ns + (size_t)r * NN, tmp + (size_t)r * NN * F);
    for (int r = 0; r < RR; r++)
        agg_k<<<agg_blocks, T>>>(r, tmp + (size_t)r * NN * F, b2, out,
                                 r == 0, r == RR - 1, 0);
}

// round 6
// speedup vs baseline: 2.4040x; 1.2363x over previous
#include <cuda_runtime.h>
#include <cuda_bf16.h>
#include <cuda_fp16.h>
#include <cstdint>

#define NN 100000
#define RR 3
#define EE 800000
#define F  128

// ---------------- scratch (device globals: allocation-free rule) ----------
__device__ __half g_tmp3[(size_t)RR * NN * F]; // per-relation GEMM outputs (fp16)
__device__ float  g_act[(size_t)NN * F];       // layer-1 activations
__device__ float  g_ns[RR * NN];               // rsqrt(max(deg_out,1))
__device__ float  g_nd[RR * NN];               // counts, then rsqrt(max(deg_in,1))
__device__ int    g_off[RR * NN];              // CSR offsets (per relation, by dst)
__device__ int    g_degi[RR * NN];             // int in-degree
__device__ int    g_cur[RR * NN];              // absolute bucket cursors
__device__ int    g_csrc[(size_t)RR * EE];     // dst-sorted src indices

// ---------------- build-chain kernels -------------------------------------
__global__ void zero_norms_k() {
    int i = blockIdx.x * blockDim.x + threadIdx.x;
    if (i < RR * NN) { g_ns[i] = 0.f; g_nd[i] = 0.f; }
}

__global__ void degree_k(const int* __restrict__ src, const int* __restrict__ dst) {
    int i = blockIdx.x * blockDim.x + threadIdx.x;
    if (i < RR * EE) {
        int r = i / EE;
        atomicAdd(&g_ns[r * NN + src[i]], 1.0f);
        atomicAdd(&g_nd[r * NN + dst[i]], 1.0f);
    }
}

// exclusive scan of int(g_nd[r]) over NN -> g_off[r], also g_degi. 1 block/rel.
__global__ void scan_k() {
    __shared__ int sh[1024];
    int r = blockIdx.x, t = threadIdx.x;
    const float* deg = g_nd + r * NN;
    const int CH = (NN + 1023) / 1024;
    int base = t * CH;
    int s = 0;
    for (int i = 0; i < CH; i++) {
        int idx = base + i;
        if (idx < NN) s += (int)deg[idx];
    }
    sh[t] = s;
    __syncthreads();
    for (int off = 1; off < 1024; off <<= 1) {
        int v = (t >= off) ? sh[t - off] : 0;
        __syncthreads();
        sh[t] += v;
        __syncthreads();
    }
    int run = sh[t] - s;
    for (int i = 0; i < CH; i++) {
        int idx = base + i;
        if (idx < NN) {
            int d = (int)deg[idx];
            g_off[r * NN + idx]  = run;
            g_degi[r * NN + idx] = d;
            run += d;
        }
    }
}

__global__ void norm_fin_k() {
    int i = blockIdx.x * blockDim.x + threadIdx.x;
    if (i < RR * NN) {
        g_ns[i] = rsqrtf(fmaxf(g_ns[i], 1.0f));
        g_nd[i] = rsqrtf(fmaxf(g_nd[i], 1.0f));
        g_cur[i] = g_off[i];                 // absolute cursors for fill
    }
}

__global__ void fill_csr_k(const int* __restrict__ src, const int* __restrict__ dst) {
    int i = blockIdx.x * blockDim.x + threadIdx.x;
    if (i < RR * EE) {
        int r = i / EE;
        int pos = atomicAdd(&g_cur[r * NN + dst[i]], 1);
        g_csrc[(size_t)r * EE + pos] = src[i];
    }
}

// ---------------- fused 3-relation tensor-core GEMM (bf16 3-term split) ---
// outp[r] = X @ W[r]  (fp16 store; per-row norm applied later in agg)
#define PA   136
#define PLANE (128 * PA)
#define GEMM_SMEM (4 * PLANE * 2)

#define MMA_BF16(d, a, b) \
    asm volatile("mma.sync.aligned.m16n8k16.row.col.f32.bf16.bf16.f32 " \
                 "{%0,%1,%2,%3}, {%4,%5,%6,%7}, {%8,%9}, {%0,%1,%2,%3};" \
                 : "+f"((d)[0]), "+f"((d)[1]), "+f"((d)[2]), "+f"((d)[3]) \
                 : "r"((a)[0]), "r"((a)[1]), "r"((a)[2]), "r"((a)[3]), \
                   "r"((b)[0]), "r"((b)[1]))

#define LDSM_X4(r, addr) \
    asm volatile("ldmatrix.sync.aligned.m8n8.x4.shared.b16 {%0,%1,%2,%3}, [%4];" \
                 : "=r"((r)[0]), "=r"((r)[1]), "=r"((r)[2]), "=r"((r)[3]) \
                 : "r"(addr))

#define LDSM_X4_T(r, addr) \
    asm volatile("ldmatrix.sync.aligned.m8n8.x4.trans.shared.b16 {%0,%1,%2,%3}, [%4];" \
                 : "=r"((r)[0]), "=r"((r)[1]), "=r"((r)[2]), "=r"((r)[3]) \
                 : "r"(addr))

__device__ __forceinline__ void split2(float x, float y,
                                       __nv_bfloat162& hi, __nv_bfloat162& lo) {
    __nv_bfloat16 hx = __float2bfloat16_rn(x);
    __nv_bfloat16 hy = __float2bfloat16_rn(y);
    hi.x = hx; hi.y = hy;
    lo.x = __float2bfloat16_rn(x - __bfloat162float(hx));
    lo.y = __float2bfloat16_rn(y - __bfloat162float(hy));
}

__global__ void __launch_bounds__(256)
gemm3_k(const float* __restrict__ X, const float* __restrict__ Wall,
        __half* __restrict__ outp) {
    extern __shared__ __align__(16) __nv_bfloat16 sh[];
    __nv_bfloat16* Ah = sh;
    __nv_bfloat16* Al = sh + PLANE;
    __nv_bfloat16* Bh = sh + 2 * PLANE;
    __nv_bfloat16* Bl = sh + 3 * PLANE;

    int t = threadIdx.x;
    int row0 = blockIdx.x * 128;

    // ---- fill A once: 128x128 fp32 -> bf16 hi/lo, [m][k] ----
#pragma unroll
    for (int i = 0; i < 16; i++) {
        int f   = t + 256 * i;
        int row = f >> 5;
        int c4  = (f & 31) << 2;
        int grow = row0 + row;
        float4 v = make_float4(0.f, 0.f, 0.f, 0.f);
        if (grow < NN) v = *reinterpret_cast<const float4*>(X + (size_t)grow * F + c4);
        __nv_bfloat162 h0, l0, h1, l1;
        split2(v.x, v.y, h0, l0);
        split2(v.z, v.w, h1, l1);
        int base = row * PA + c4;
        *reinterpret_cast<__nv_bfloat162*>(&Ah[base])     = h0;
        *reinterpret_cast<__nv_bfloat162*>(&Ah[base + 2]) = h1;
        *reinterpret_cast<__nv_bfloat162*>(&Al[base])     = l0;
        *reinterpret_cast<__nv_bfloat162*>(&Al[base + 2]) = l1;
    }

    int lane = t & 31, warp = t >> 5;
    int mbase = (warp & 3) * 32;
    int nbase = (warp >> 2) * 64;

    int lrow = lane & 7;
    int m8   = ((lane >> 3) & 1) << 3;
    int k8   = ((lane >> 4) & 1) << 3;

    unsigned aA0 = (unsigned)__cvta_generic_to_shared(
        &Ah[(mbase + lrow + m8) * PA + k8]);
    unsigned aA1 = aA0 + 16 * PA * 2;
    unsigned aLoOff = PLANE * 2;
    unsigned aB0 = (unsigned)__cvta_generic_to_shared(
        &Bh[(lrow + m8) * PA + nbase + k8]);

    int grp = lane >> 2;
    int cof = (lane & 3) * 2;

    for (int r = 0; r < RR; r++) {
        __syncthreads();   // prior-iteration B reads done (and A fill on r=0)
        const float* W = Wall + (size_t)r * F * F;
#pragma unroll
        for (int i = 0; i < 16; i++) {
            int f  = t + 256 * i;
            int k  = f >> 5;
            int n4 = (f & 31) << 2;
            float4 v = *reinterpret_cast<const float4*>(W + (size_t)k * F + n4);
            __nv_bfloat162 h0, l0, h1, l1;
            split2(v.x, v.y, h0, l0);
            split2(v.z, v.w, h1, l1);
            int base = k * PA + n4;
            *reinterpret_cast<__nv_bfloat162*>(&Bh[base])     = h0;
            *reinterpret_cast<__nv_bfloat162*>(&Bh[base + 2]) = h1;
            *reinterpret_cast<__nv_bfloat162*>(&Bl[base])     = l0;
            *reinterpret_cast<__nv_bfloat162*>(&Bl[base + 2]) = l1;
        }
        __syncthreads();

        float acc[2][8][4];
#pragma unroll
        for (int mt = 0; mt < 2; mt++)
#pragma unroll
            for (int nt = 0; nt < 8; nt++)
#pragma unroll
                for (int c = 0; c < 4; c++) acc[mt][nt][c] = 0.f;

#pragma unroll
        for (int kc = 0; kc < 8; kc++) {
            unsigned aOff = kc * 32;
            unsigned bOff = kc * 16 * PA * 2;

            unsigned ah[2][4], al[2][4];
            LDSM_X4(ah[0], aA0 + aOff);
            LDSM_X4(ah[1], aA1 + aOff);
            LDSM_X4(al[0], aA0 + aLoOff + aOff);
            LDSM_X4(al[1], aA1 + aLoOff + aOff);

#pragma unroll
            for (int np = 0; np < 4; np++) {
                unsigned bAddr = aB0 + bOff + np * 16 * 2;
                unsigned bh[4], bl[4];
                LDSM_X4_T(bh, bAddr);
                LDSM_X4_T(bl, bAddr + aLoOff);
                unsigned* bh0 = bh;
                unsigned* bh1 = bh + 2;
                unsigned* bl0 = bl;
                unsigned* bl1 = bl + 2;
#pragma unroll
                for (int mt = 0; mt < 2; mt++) {
                    MMA_BF16(acc[mt][2 * np],     ah[mt], bh0);
                    MMA_BF16(acc[mt][2 * np],     ah[mt], bl0);
                    MMA_BF16(acc[mt][2 * np],     al[mt], bh0);
                    MMA_BF16(acc[mt][2 * np + 1], ah[mt], bh1);
                    MMA_BF16(acc[mt][2 * np + 1], ah[mt], bl1);
                    MMA_BF16(acc[mt][2 * np + 1], al[mt], bh1);
                }
            }
        }

        __half* op = outp + (size_t)r * NN * F;
#pragma unroll
        for (int mt = 0; mt < 2; mt++) {
            int rA = row0 + mbase + mt * 16 + grp;
            int rB = rA + 8;
#pragma unroll
            for (int nt = 0; nt < 8; nt++) {
                int col = nbase + nt * 8 + cof;
                if (rA < NN)
                    *reinterpret_cast<__half2*>(op + (size_t)rA * F + col) =
                        __floats2half2_rn(acc[mt][nt][0], acc[mt][nt][1]);
                if (rB < NN)
                    *reinterpret_cast<__half2*>(op + (size_t)rB * F + col) =
                        __floats2half2_rn(acc[mt][nt][2], acc[mt][nt][3]);
            }
        }
    }
}

// ---------------- fused aggregation: one warp per node, all 3 relations ---
// out[node] = sum_r nd_r[node] * (sum_{e in CSR[r][node]} tmp_r[src_e]*ns_r[src_e])
//           + sum_r bias_r    (+ optional ReLU)
__global__ void __launch_bounds__(256)
agg_all_k(const __half* __restrict__ tmp3, const float* __restrict__ bias,
          float* __restrict__ outp, int relu) {
    int warp = (blockIdx.x * blockDim.x + threadIdx.x) >> 5;
    int lane = threadIdx.x & 31;
    if (warp >= NN) return;
    int node = warp;
    int c4 = lane * 4;

    float4 acc;
    {
        float4 b0 = *reinterpret_cast<const float4*>(bias + c4);
        float4 b1 = *reinterpret_cast<const float4*>(bias + F + c4);
        float4 b2 = *reinterpret_cast<const float4*>(bias + 2 * F + c4);
        acc = make_float4(b0.x + b1.x + b2.x, b0.y + b1.y + b2.y,
                          b0.z + b1.z + b2.z, b0.w + b1.w + b2.w);
    }

#pragma unroll
    for (int r = 0; r < RR; r++) {
        int off = g_off[r * NN + node];
        int cnt = g_degi[r * NN + node];
        const int* lst = g_csrc + (size_t)r * EE + off;
        const float* nsr = g_ns + r * NN;
        const __half* tmp = tmp3 + (size_t)r * NN * F;

        float4 part = make_float4(0.f, 0.f, 0.f, 0.f);
        int j = 0;
        for (; j + 4 <= cnt; j += 4) {
            int s0 = __ldg(lst + j);
            int s1 = __ldg(lst + j + 1);
            int s2 = __ldg(lst + j + 2);
            int s3 = __ldg(lst + j + 3);
            float n0 = __ldg(nsr + s0), n1 = __ldg(nsr + s1);
            float n2 = __ldg(nsr + s2), n3 = __ldg(nsr + s3);
            uint2 w0 = *reinterpret_cast<const uint2*>(tmp + (size_t)s0 * F + c4);
            uint2 w1 = *reinterpret_cast<const uint2*>(tmp + (size_t)s1 * F + c4);
            uint2 w2 = *reinterpret_cast<const uint2*>(tmp + (size_t)s2 * F + c4);
            uint2 w3 = *reinterpret_cast<const uint2*>(tmp + (size_t)s3 * F + c4);
            float2 a0 = __half22float2(*reinterpret_cast<__half2*>(&w0.x));
            float2 c0 = __half22float2(*reinterpret_cast<__half2*>(&w0.y));
            float2 a1 = __half22float2(*reinterpret_cast<__half2*>(&w1.x));
            float2 c1 = __half22float2(*reinterpret_cast<__half2*>(&w1.y));
            float2 a2 = __half22float2(*reinterpret_cast<__half2*>(&w2.x));
            float2 c2 = __half22float2(*reinterpret_cast<__half2*>(&w2.y));
            float2 a3 = __half22float2(*reinterpret_cast<__half2*>(&w3.x));
            float2 c3 = __half22float2(*reinterpret_cast<__half2*>(&w3.y));
            part.x += a0.x * n0 + a1.x * n1 + a2.x * n2 + a3.x * n3;
            part.y += a0.y * n0 + a1.y * n1 + a2.y * n2 + a3.y * n3;
            part.z += c0.x * n0 + c1.x * n1 + c2.x * n2 + c3.x * n3;
            part.w += c0.y * n0 + c1.y * n1 + c2.y * n2 + c3.y * n3;
        }
        for (; j < cnt; j++) {
            int s = __ldg(lst + j);
            float n = __ldg(nsr + s);
            uint2 w = *reinterpret_cast<const uint2*>(tmp + (size_t)s * F + c4);
            float2 a = __half22float2(*reinterpret_cast<__half2*>(&w.x));
            float2 c = __half22float2(*reinterpret_cast<__half2*>(&w.y));
            part.x += a.x * n; part.y += a.y * n;
            part.z += c.x * n; part.w += c.y * n;
        }

        float nd = g_nd[r * NN + node];
        acc.x += part.x * nd; acc.y += part.y * nd;
        acc.z += part.z * nd; acc.w += part.w * nd;
    }

    if (relu) {
        acc.x = fmaxf(acc.x, 0.f); acc.y = fmaxf(acc.y, 0.f);
        acc.z = fmaxf(acc.z, 0.f); acc.w = fmaxf(acc.w, 0.f);
    }
    *reinterpret_cast<float4*>(outp + (size_t)node * F + c4) = acc;
}

// ---------------- launch ---------------------------------------------------
extern "C" void kernel_launch(void* const* d_in, const int* in_sizes, int n_in,
                              void* d_out, int out_size) {
    const float* x   = (const float*)d_in[0];
    const int*   src = (const int*)  d_in[1];
    const int*   dst = (const int*)  d_in[2];
    const float* W1  = (const float*)d_in[3];
    const float* b1  = (const float*)d_in[4];
    const float* W2  = (const float*)d_in[5];
    const float* b2  = (const float*)d_in[6];
    float* out = (float*)d_out;

    void* p;
    cudaGetSymbolAddress(&p, g_act);  float*  act = (float*)p;
    cudaGetSymbolAddress(&p, g_tmp3); __half* tmp = (__half*)p;

    cudaFuncSetAttribute(gemm3_k,
                         cudaFuncAttributeMaxDynamicSharedMemorySize, GEMM_SMEM);

    const int T = 256;
    int gemm_blocks = (NN + 127) / 128;
    int agg_blocks  = (NN * 32 + T - 1) / T;

    // ---- CSR build ----
    zero_norms_k<<<(RR * NN + T - 1) / T, T>>>();
    degree_k<<<(RR * EE + T - 1) / T, T>>>(src, dst);
    scan_k<<<RR, 1024>>>();
    norm_fin_k<<<(RR * NN + T - 1) / T, T>>>();
    fill_csr_k<<<(RR * EE + T - 1) / T, T>>>(src, dst);

    // ---- layer 1 ----
    gemm3_k<<<gemm_blocks, T, GEMM_SMEM>>>(x, W1, tmp);
    agg_all_k<<<agg_blocks, T>>>(tmp, b1, act, 1);

    // ---- layer 2 ----
    gemm3_k<<<gemm_blocks, T, GEMM_SMEM>>>(act, W2, tmp);
    agg_all_k<<<agg_blocks, T>>>(tmp, b2, out, 0);
}